// round 11
// baseline (speedup 1.0000x reference)
#include <cuda_runtime.h>
#include <cstdint>

// Problem constants: B=131072, T=40, H=40, C=4
#define TT   40
#define HH   40
#define UPT  5            // hidden units per lane (8 subs cover H=40)
#define NSEQ 4            // sequences per lane (dual accumulators force 4)
#define SEQ_PER_WARP 16
#define SEQ_PER_CTA  64

typedef unsigned long long ull;

// ---- packed fp32x2 helpers (sm_103a: FFMA2 only via PTX) ----
__device__ __forceinline__ ull ffma2(ull a, ull b, ull c) {
    ull d;
    asm("fma.rn.f32x2 %0, %1, %2, %3;" : "=l"(d) : "l"(a), "l"(b), "l"(c));
    return d;
}
__device__ __forceinline__ ull pack2(float lo, float hi) {
    ull r;
    asm("mov.b64 %0, {%1, %2};" : "=l"(r) : "f"(lo), "f"(hi));
    return r;
}
__device__ __forceinline__ void unpack2(ull v, float& lo, float& hi) {
    asm("mov.b64 {%0, %1}, %2;" : "=f"(lo), "=f"(hi) : "l"(v));
}
__device__ __forceinline__ ull pack_bits(float lo, float hi) {
    return (ull)__float_as_uint(lo) | ((ull)__float_as_uint(hi) << 32);
}

// ---- MUFU primitives ----
__device__ __forceinline__ float ex2f(float x) {
    float r; asm("ex2.approx.f32 %0, %1;" : "=f"(r) : "f"(x)); return r;
}
__device__ __forceinline__ float rcpf(float x) {
    float r; asm("rcp.approx.f32 %0, %1;" : "=f"(r) : "f"(x)); return r;
}

#define NLOG2E (-1.4426950408889634f)
#define TLOG2E ( 2.8853901817779268f)  // 2*log2(e)

// Weight row per (sub, k): 12 ull slots, [0..4]=(i,f) pairs, [5..9]=(g,o) pairs.
// Per-sub stride 482 ull (16B stagger) -> conflict-free LDS.128 wavefronts.
#define WROW 12
#define SUBSTRIDE 482

// ---- epilogue slice j: consume aold[.][j], update c/h[.][j] (shared-RCP form) ----
//   c_new = [c*D1*V1 + (v-1)*D2] / (D2*D1*V1);  h_new = (w-1)/((1+e^-o)(w+1))
// Range audit: |gates|<~8, c<=T=40 -> max ex2 exponent ~115 < 126. Safe.
#define EPI_SLICE(j, AIF, AGO)                                              \
    _Pragma("unroll")                                                       \
    for (int s = 0; s < NSEQ; s++) {                                        \
        float ig, fg, gg, og;                                               \
        unpack2(AIF[s][j], ig, fg);                                         \
        unpack2(AGO[s][j], gg, og);                                         \
        const float u_  = ex2f(ig * NLOG2E);                                \
        const float fe  = ex2f(fg * NLOG2E);                                \
        const float v_  = ex2f(gg * TLOG2E);                                \
        const float D1  = 1.0f + u_;                                        \
        const float D2  = 1.0f + fe;                                        \
        const float V1  = v_ + 1.0f;                                        \
        const float Vm  = v_ - 1.0f;                                        \
        const float D1V1 = D1 * V1;                                         \
        const float num  = fmaf(c[s][j], D1V1, Vm * D2);                    \
        const float cn   = num * rcpf(D2 * D1V1);                           \
        c[s][j] = cn;                                                       \
        const float oe = ex2f(og * NLOG2E);                                 \
        const float w_ = ex2f(cn * TLOG2E);                                 \
        const float r2 = rcpf((1.0f + oe) * (w_ + 1.0f));                   \
        h[s][j] = (w_ - 1.0f) * r2;                                         \
    }

// ---- k-loop slice kk=j: rows k = m*5+j, accumulate into ANEW ----
#define KLOOP_SLICE(j, AIF, AGO)                                            \
    _Pragma("unroll")                                                       \
    for (int m = 0; m < 8; m++) {                                           \
        float hs[NSEQ];                                                     \
        _Pragma("unroll")                                                   \
        for (int s = 0; s < NSEQ; s++)                                      \
            hs[s] = __shfl_sync(0xffffffffu, h[s][j], m, 8);                \
        const char* row = wbase + (size_t)(m * UPT + (j)) * (WROW * 8);     \
        const ulonglong2 w01 = *reinterpret_cast<const ulonglong2*>(row);   \
        const ulonglong2 w23 = *reinterpret_cast<const ulonglong2*>(row + 16); \
        const ulonglong2 wg0 = *reinterpret_cast<const ulonglong2*>(row + 32); \
        const ulonglong2 g12 = *reinterpret_cast<const ulonglong2*>(row + 48); \
        const ulonglong2 g34 = *reinterpret_cast<const ulonglong2*>(row + 64); \
        _Pragma("unroll")                                                   \
        for (int s = 0; s < NSEQ; s++) {                                    \
            const ull hk2 = pack2(hs[s], hs[s]);                            \
            AIF[s][0] = ffma2(hk2, w01.x, AIF[s][0]);                       \
            AIF[s][1] = ffma2(hk2, w01.y, AIF[s][1]);                       \
            AIF[s][2] = ffma2(hk2, w23.x, AIF[s][2]);                       \
            AIF[s][3] = ffma2(hk2, w23.y, AIF[s][3]);                       \
            AIF[s][4] = ffma2(hk2, wg0.x, AIF[s][4]);                       \
            AGO[s][0] = ffma2(hk2, wg0.y, AGO[s][0]);                       \
            AGO[s][1] = ffma2(hk2, g12.x, AGO[s][1]);                       \
            AGO[s][2] = ffma2(hk2, g12.y, AGO[s][2]);                       \
            AGO[s][3] = ffma2(hk2, g34.x, AGO[s][3]);                       \
            AGO[s][4] = ffma2(hk2, g34.y, AGO[s][4]);                       \
        }                                                                   \
    }

#define GINIT(AIF, AGO, t)                                                  \
    _Pragma("unroll")                                                       \
    for (int s = 0; s < NSEQ; s++) {                                        \
        const float xv = sx0[s * (TT + 1) + (t)];                           \
        const ull xt2 = pack2(xv, xv);                                      \
        _Pragma("unroll")                                                   \
        for (int jj = 0; jj < UPT; jj++) {                                  \
            AIF[s][jj] = ffma2(xt2, sWinIf[u0 + jj], sBif[u0 + jj]);        \
            AGO[s][jj] = ffma2(xt2, sWinGo[u0 + jj], sBgo[u0 + jj]);        \
        }                                                                   \
    }

// Full pipelined step: epi(t-1) slices interleaved into kloop(t).
// epi(j+1) is placed BEFORE kloop(j) so its MUFU chain hides under FMA.
#define STEP_MID(t, OLDIF, OLDGO, NEWIF, NEWGO)                             \
    do {                                                                    \
        GINIT(NEWIF, NEWGO, t);                                             \
        EPI_SLICE(0, OLDIF, OLDGO);                                         \
        EPI_SLICE(1, OLDIF, OLDGO);                                         \
        KLOOP_SLICE(0, NEWIF, NEWGO);                                       \
        EPI_SLICE(2, OLDIF, OLDGO);                                         \
        KLOOP_SLICE(1, NEWIF, NEWGO);                                       \
        EPI_SLICE(3, OLDIF, OLDGO);                                         \
        KLOOP_SLICE(2, NEWIF, NEWGO);                                       \
        EPI_SLICE(4, OLDIF, OLDGO);                                         \
        KLOOP_SLICE(3, NEWIF, NEWGO);                                       \
        KLOOP_SLICE(4, NEWIF, NEWGO);                                       \
    } while (0)

__global__ __launch_bounds__(128)
void lstm_fused_kernel(const float* __restrict__ x,
                       const float* __restrict__ W_ih,
                       const float* __restrict__ W_hh,
                       const float* __restrict__ b_ih,
                       const float* __restrict__ b_hh,
                       const float* __restrict__ W_fc,
                       const float* __restrict__ b_fc,
                       float* __restrict__ out,
                       int B, int out_size)
{
    __shared__ __align__(16) ull sW[8 * SUBSTRIDE];           // 30.8 KB
    __shared__ __align__(16) ull sBif[HH], sBgo[HH], sWinIf[HH], sWinGo[HH];
    __shared__ float sWfc[4 * HH];
    __shared__ float sbfc[4];
    __shared__ float sx[SEQ_PER_CTA * (TT + 1)];              // padded rows

    const int tid = threadIdx.x;
    const int seq_base = blockIdx.x * SEQ_PER_CTA;

    // ---- fill packed weights ----
    for (int idx = tid; idx < HH * HH; idx += blockDim.x) {
        int k = idx / HH, u = idx % HH;
        int sub = u / UPT, j = u % UPT;
        ull* row = &sW[sub * SUBSTRIDE + k * WROW];
        row[j]     = pack_bits(W_hh[u * HH + k],          W_hh[(HH + u) * HH + k]);
        row[5 + j] = pack_bits(W_hh[(2*HH + u) * HH + k], W_hh[(3*HH + u) * HH + k]);
    }
    for (int u = tid; u < HH; u += blockDim.x) {
        sBif[u]   = pack_bits(b_ih[u]        + b_hh[u],        b_ih[HH + u]   + b_hh[HH + u]);
        sBgo[u]   = pack_bits(b_ih[2*HH + u] + b_hh[2*HH + u], b_ih[3*HH + u] + b_hh[3*HH + u]);
        sWinIf[u] = pack_bits(W_ih[u],        W_ih[HH + u]);
        sWinGo[u] = pack_bits(W_ih[2*HH + u], W_ih[3*HH + u]);
    }
    for (int i = tid; i < 4 * HH; i += blockDim.x) sWfc[i] = W_fc[i];
    if (tid < 4) sbfc[tid] = b_fc[tid];

    // ---- stage x (coalesced) ----
    for (int idx = tid; idx < SEQ_PER_CTA * TT; idx += blockDim.x) {
        int sq = idx / TT, t = idx % TT;
        int gb = seq_base + sq;
        sx[sq * (TT + 1) + t] = (gb < B) ? x[(size_t)gb * TT + t] : 0.0f;
    }
    __syncthreads();

    const int lane = tid & 31;
    const int w    = tid >> 5;
    const int sub  = lane & 7;          // unit slice: [sub*5, sub*5+5)
    const int grp  = lane >> 3;         // sequence group within warp
    const int u0   = sub * UPT;
    const int sq0  = w * SEQ_PER_WARP + grp * NSEQ;

    const char* __restrict__ wbase = (const char*)&sW[sub * SUBSTRIDE];
    const float* __restrict__ sx0  = &sx[sq0 * (TT + 1)];

    float h[NSEQ][UPT], c[NSEQ][UPT];
    ull a1if[NSEQ][UPT], a1go[NSEQ][UPT];
    ull a2if[NSEQ][UPT], a2go[NSEQ][UPT];
#pragma unroll
    for (int s = 0; s < NSEQ; s++)
#pragma unroll
        for (int j = 0; j < UPT; j++) { h[s][j] = 0.0f; c[s][j] = 0.0f; }

    // Prologue: h(init)=0 -> step-0 gates are exactly the ginit values
    // (the h@W_hh contribution is identically zero); skip the t=0 k-loop.
    GINIT(a1if, a1go, 0);

    // Pipelined mid steps: epi of step t-1 interleaved into kloop of step t.
    // 19 pairs cover t = 1..38; one extra body covers t = 39.
    for (int t = 1; t < 39; t += 2) {
        STEP_MID(t,     a1if, a1go, a2if, a2go);
        STEP_MID(t + 1, a2if, a2go, a1if, a1go);
    }
    STEP_MID(39, a1if, a1go, a2if, a2go);

    // Final epilogue: gates of step 39 live in a2.
    EPI_SLICE(0, a2if, a2go);
    EPI_SLICE(1, a2if, a2go);
    EPI_SLICE(2, a2if, a2go);
    EPI_SLICE(3, a2if, a2go);
    EPI_SLICE(4, a2if, a2go);

    // ---- FC head: per-lane partials, xor-reduce over the 8-lane sub group ----
    float lg[NSEQ][4];
#pragma unroll
    for (int s = 0; s < NSEQ; s++) {
#pragma unroll
        for (int cc = 0; cc < 4; cc++) {
            float p = 0.0f;
#pragma unroll
            for (int j = 0; j < UPT; j++) p = fmaf(h[s][j], sWfc[cc * HH + u0 + j], p);
            p += __shfl_xor_sync(0xffffffffu, p, 1, 8);
            p += __shfl_xor_sync(0xffffffffu, p, 2, 8);
            p += __shfl_xor_sync(0xffffffffu, p, 4, 8);
            lg[s][cc] = __fadd_rn(p, sbfc[cc]);
        }
    }

    if (sub == 0) {
#pragma unroll
        for (int s = 0; s < NSEQ; s++) {
            const int b = seq_base + sq0 + s;
            if (b < B) {
                reinterpret_cast<float4*>(out)[b] =
                    make_float4(lg[s][0], lg[s][1], lg[s][2], lg[s][3]);
                if (out_size >= 5 * B) {
                    float best = lg[s][0];
                    int   bi   = 0;
#pragma unroll
                    for (int cc = 1; cc < 4; cc++) {
                        if (lg[s][cc] > best) { best = lg[s][cc]; bi = cc; }
                    }
                    out[(size_t)4 * B + b] = (float)bi;
                }
            }
        }
    }
}

extern "C" void kernel_launch(void* const* d_in, const int* in_sizes, int n_in,
                              void* d_out, int out_size)
{
    const float* x    = (const float*)d_in[0];
    const float* W_ih = (const float*)d_in[1];
    const float* W_hh = (const float*)d_in[2];
    const float* b_ih = (const float*)d_in[3];
    const float* b_hh = (const float*)d_in[4];
    const float* W_fc = (const float*)d_in[5];
    const float* b_fc = (const float*)d_in[6];

    const int B = in_sizes[0] / TT;
    const int threads = 128;
    const int blocks  = (B + SEQ_PER_CTA - 1) / SEQ_PER_CTA;

    lstm_fused_kernel<<<blocks, threads>>>(x, W_ih, W_hh, b_ih, b_hh,
                                           W_fc, b_fc, (float*)d_out, B, out_size);
}

// round 12
// speedup vs baseline: 5.9832x; 5.9832x over previous
#include <cuda_runtime.h>
#include <cstdint>

// Problem constants: B=131072, T=40, H=40, C=4
#define TT   40
#define HH   40
#define UPT  5            // hidden units per lane (8 subs cover H=40)
#define NSEQ 4            // sequences per lane
#define SEQ_PER_WARP 16
#define SEQ_PER_CTA  64

typedef unsigned long long ull;

// ---- packed fp32x2 helpers (sm_103a: FFMA2 only via PTX) ----
__device__ __forceinline__ ull ffma2(ull a, ull b, ull c) {
    ull d;
    asm("fma.rn.f32x2 %0, %1, %2, %3;" : "=l"(d) : "l"(a), "l"(b), "l"(c));
    return d;
}
__device__ __forceinline__ ull pack2(float lo, float hi) {
    ull r;
    asm("mov.b64 %0, {%1, %2};" : "=l"(r) : "f"(lo), "f"(hi));
    return r;
}
__device__ __forceinline__ void unpack2(ull v, float& lo, float& hi) {
    asm("mov.b64 {%0, %1}, %2;" : "=f"(lo), "=f"(hi) : "l"(v));
}
__device__ __forceinline__ ull pack_bits(float lo, float hi) {
    return (ull)__float_as_uint(lo) | ((ull)__float_as_uint(hi) << 32);
}

// ---- MUFU primitives ----
__device__ __forceinline__ float ex2f(float x) {
    float r; asm("ex2.approx.f32 %0, %1;" : "=f"(r) : "f"(x)); return r;
}
__device__ __forceinline__ float rcpf(float x) {
    float r; asm("rcp.approx.f32 %0, %1;" : "=f"(r) : "f"(x)); return r;
}

#define NLOG2E (-1.4426950408889634f)
#define TLOG2E ( 2.8853901817779268f)  // 2*log2(e)

// Weight row per (sub, k): 12 ull slots (96B stride keeps 16B alignment).
// A-part (units 0..2): slot0=(i,f)u0 slot1=(i,f)u1 slot2=(i,f)u2
//                      slot3=(g,o)u0 slot4=(g,o)u1 slot5=(g,o)u2
// B-part (units 3..4): slot6=(i,f)u3 slot7=(i,f)u4 slot8=(g,o)u3 slot9=(g,o)u4
// -> kloopA reads 3 LDS.128/row, kloopB reads 2; 5 total (unchanged).
// Per-sub stride 482 ull: 16B stagger -> conflict-free wavefronts.
#define WROW 12
#define SUBSTRIDE 482

// ---- activation for one unit (shared-RCP fused form, 7 MUFU) ----
// c_new = [c*D1*V1 + (v-1)*D2] / (D2*D1*V1);  h_new = (w-1)/((1+e^-o)(w+1))
// Range audit: |gates|<~8, c<=T=40 -> max ex2 exponent ~115 < 126. Safe.
__device__ __forceinline__ void lstm_unit(ull aif, ull ago, float& cc, float& hh) {
    float ig, fg, gg, og;
    unpack2(aif, ig, fg);
    unpack2(ago, gg, og);
    const float u_  = ex2f(ig * NLOG2E);
    const float fe  = ex2f(fg * NLOG2E);
    const float v_  = ex2f(gg * TLOG2E);
    const float D1  = 1.0f + u_;
    const float D2  = 1.0f + fe;
    const float V1  = v_ + 1.0f;
    const float Vm  = v_ - 1.0f;
    const float D1V1 = D1 * V1;
    const float num  = fmaf(cc, D1V1, Vm * D2);
    const float cn   = num * rcpf(D2 * D1V1);
    cc = cn;
    const float oe = ex2f(og * NLOG2E);
    const float w_ = ex2f(cn * TLOG2E);
    const float r2 = rcpf((1.0f + oe) * (w_ + 1.0f));
    hh = (w_ - 1.0f) * r2;
}

__global__ __launch_bounds__(128)
void lstm_fused_kernel(const float* __restrict__ x,
                       const float* __restrict__ W_ih,
                       const float* __restrict__ W_hh,
                       const float* __restrict__ b_ih,
                       const float* __restrict__ b_hh,
                       const float* __restrict__ W_fc,
                       const float* __restrict__ b_fc,
                       float* __restrict__ out,
                       int B, int out_size)
{
    __shared__ __align__(16) ull sW[8 * SUBSTRIDE];           // 30.8 KB
    __shared__ __align__(16) ull sBif[HH], sBgo[HH], sWinIf[HH], sWinGo[HH];
    __shared__ float sWfc[4 * HH];
    __shared__ float sbfc[4];
    __shared__ float sx[SEQ_PER_CTA * (TT + 1)];              // padded rows

    const int tid = threadIdx.x;
    const int seq_base = blockIdx.x * SEQ_PER_CTA;

    // ---- fill packed weights (A/B split slot layout) ----
    for (int idx = tid; idx < HH * HH; idx += blockDim.x) {
        int k = idx / HH, u = idx % HH;
        int sub = u / UPT, j = u % UPT;
        int ifslot = (j < 3) ? j       : 6 + (j - 3);
        int goslot = (j < 3) ? 3 + j   : 8 + (j - 3);
        ull* row = &sW[sub * SUBSTRIDE + k * WROW];
        row[ifslot] = pack_bits(W_hh[u * HH + k],          W_hh[(HH + u) * HH + k]);
        row[goslot] = pack_bits(W_hh[(2*HH + u) * HH + k], W_hh[(3*HH + u) * HH + k]);
    }
    for (int u = tid; u < HH; u += blockDim.x) {
        sBif[u]   = pack_bits(b_ih[u]        + b_hh[u],        b_ih[HH + u]   + b_hh[HH + u]);
        sBgo[u]   = pack_bits(b_ih[2*HH + u] + b_hh[2*HH + u], b_ih[3*HH + u] + b_hh[3*HH + u]);
        sWinIf[u] = pack_bits(W_ih[u],        W_ih[HH + u]);
        sWinGo[u] = pack_bits(W_ih[2*HH + u], W_ih[3*HH + u]);
    }
    for (int i = tid; i < 4 * HH; i += blockDim.x) sWfc[i] = W_fc[i];
    if (tid < 4) sbfc[tid] = b_fc[tid];

    // ---- stage x (coalesced) ----
    for (int idx = tid; idx < SEQ_PER_CTA * TT; idx += blockDim.x) {
        int sq = idx / TT, t = idx % TT;
        int gb = seq_base + sq;
        sx[sq * (TT + 1) + t] = (gb < B) ? x[(size_t)gb * TT + t] : 0.0f;
    }
    __syncthreads();

    const int lane = tid & 31;
    const int w    = tid >> 5;
    const int sub  = lane & 7;          // unit slice: [sub*5, sub*5+5)
    const int grp  = lane >> 3;         // sequence group within warp
    const int u0   = sub * UPT;
    const int sq0  = w * SEQ_PER_WARP + grp * NSEQ;

    const char* __restrict__ wbase = (const char*)&sW[sub * SUBSTRIDE];
    const float* __restrict__ sx0  = &sx[sq0 * (TT + 1)];

    float h[NSEQ][UPT], c[NSEQ][UPT], hold[NSEQ][UPT];
#pragma unroll
    for (int s = 0; s < NSEQ; s++)
#pragma unroll
        for (int j = 0; j < UPT; j++) { h[s][j] = 0.0f; c[s][j] = 0.0f; }

    for (int t = 0; t < TT; t++) {
        // snapshot h: both kloops shuffle from hold; epi writes h
#pragma unroll
        for (int s = 0; s < NSEQ; s++)
#pragma unroll
            for (int j = 0; j < UPT; j++) hold[s][j] = h[s][j];

        // ---- gate init (bias + x*W_in), A and B parts ----
        ull aAif[NSEQ][3], aAgo[NSEQ][3];
        ull aBif[NSEQ][2], aBgo[NSEQ][2];
#pragma unroll
        for (int s = 0; s < NSEQ; s++) {
            const float xv = sx0[s * (TT + 1) + t];
            const ull xt2 = pack2(xv, xv);
#pragma unroll
            for (int j = 0; j < 3; j++) {
                aAif[s][j] = ffma2(xt2, sWinIf[u0 + j], sBif[u0 + j]);
                aAgo[s][j] = ffma2(xt2, sWinGo[u0 + j], sBgo[u0 + j]);
            }
#pragma unroll
            for (int j = 0; j < 2; j++) {
                aBif[s][j] = ffma2(xt2, sWinIf[u0 + 3 + j], sBif[u0 + 3 + j]);
                aBgo[s][j] = ffma2(xt2, sWinGo[u0 + 3 + j], sBgo[u0 + 3 + j]);
            }
        }

        // ---- kloopA: all 40 k rows, units 0..2 (3 LDS.128/row) ----
        for (int m = 0; m < 8; m++) {
            float hk[UPT][NSEQ];
#pragma unroll
            for (int kk = 0; kk < UPT; kk++)
#pragma unroll
                for (int s = 0; s < NSEQ; s++)
                    hk[kk][s] = __shfl_sync(0xffffffffu, hold[s][kk], m, 8);

            const char* base = wbase + (size_t)m * (UPT * WROW * 8);
#pragma unroll
            for (int kk = 0; kk < UPT; kk++) {
                const char* row = base + kk * (WROW * 8);
                const ulonglong2 a01 = *reinterpret_cast<const ulonglong2*>(row);      // if0,if1
                const ulonglong2 a23 = *reinterpret_cast<const ulonglong2*>(row + 16); // if2,go0
                const ulonglong2 a45 = *reinterpret_cast<const ulonglong2*>(row + 32); // go1,go2
#pragma unroll
                for (int s = 0; s < NSEQ; s++) {
                    const ull hk2 = pack2(hk[kk][s], hk[kk][s]);
                    aAif[s][0] = ffma2(hk2, a01.x, aAif[s][0]);
                    aAif[s][1] = ffma2(hk2, a01.y, aAif[s][1]);
                    aAif[s][2] = ffma2(hk2, a23.x, aAif[s][2]);
                    aAgo[s][0] = ffma2(hk2, a23.y, aAgo[s][0]);
                    aAgo[s][1] = ffma2(hk2, a45.x, aAgo[s][1]);
                    aAgo[s][2] = ffma2(hk2, a45.y, aAgo[s][2]);
                }
            }
        }

        // ---- epiA (units 0..2): MUFU chains, independent of kloopB below ----
#pragma unroll
        for (int s = 0; s < NSEQ; s++)
#pragma unroll
            for (int j = 0; j < 3; j++)
                lstm_unit(aAif[s][j], aAgo[s][j], c[s][j], h[s][j]);

        // ---- kloopB: all 40 k rows, units 3..4 (2 LDS.128/row) ----
        // reads only hold + aB -> no dependency on epiA; ptxas interleaves.
        for (int m = 0; m < 8; m++) {
            float hk[UPT][NSEQ];
#pragma unroll
            for (int kk = 0; kk < UPT; kk++)
#pragma unroll
                for (int s = 0; s < NSEQ; s++)
                    hk[kk][s] = __shfl_sync(0xffffffffu, hold[s][kk], m, 8);

            const char* base = wbase + (size_t)m * (UPT * WROW * 8);
#pragma unroll
            for (int kk = 0; kk < UPT; kk++) {
                const char* row = base + kk * (WROW * 8);
                const ulonglong2 b67 = *reinterpret_cast<const ulonglong2*>(row + 48); // if3,if4
                const ulonglong2 b89 = *reinterpret_cast<const ulonglong2*>(row + 64); // go3,go4
#pragma unroll
                for (int s = 0; s < NSEQ; s++) {
                    const ull hk2 = pack2(hk[kk][s], hk[kk][s]);
                    aBif[s][0] = ffma2(hk2, b67.x, aBif[s][0]);
                    aBif[s][1] = ffma2(hk2, b67.y, aBif[s][1]);
                    aBgo[s][0] = ffma2(hk2, b89.x, aBgo[s][0]);
                    aBgo[s][1] = ffma2(hk2, b89.y, aBgo[s][1]);
                }
            }
        }

        // ---- epiB (units 3..4) ----
#pragma unroll
        for (int s = 0; s < NSEQ; s++)
#pragma unroll
            for (int j = 0; j < 2; j++)
                lstm_unit(aBif[s][j], aBgo[s][j], c[s][3 + j], h[s][3 + j]);
        // warp-synchronous: next step's shuffles (full-mask) see updated h
    }

    // ---- FC head: per-lane partials, xor-reduce over the 8-lane sub group ----
    float lg[NSEQ][4];
#pragma unroll
    for (int s = 0; s < NSEQ; s++) {
#pragma unroll
        for (int cc = 0; cc < 4; cc++) {
            float p = 0.0f;
#pragma unroll
            for (int j = 0; j < UPT; j++) p = fmaf(h[s][j], sWfc[cc * HH + u0 + j], p);
            p += __shfl_xor_sync(0xffffffffu, p, 1, 8);
            p += __shfl_xor_sync(0xffffffffu, p, 2, 8);
            p += __shfl_xor_sync(0xffffffffu, p, 4, 8);
            lg[s][cc] = __fadd_rn(p, sbfc[cc]);
        }
    }

    if (sub == 0) {
#pragma unroll
        for (int s = 0; s < NSEQ; s++) {
            const int b = seq_base + sq0 + s;
            if (b < B) {
                reinterpret_cast<float4*>(out)[b] =
                    make_float4(lg[s][0], lg[s][1], lg[s][2], lg[s][3]);
                if (out_size >= 5 * B) {
                    float best = lg[s][0];
                    int   bi   = 0;
#pragma unroll
                    for (int cc = 1; cc < 4; cc++) {
                        if (lg[s][cc] > best) { best = lg[s][cc]; bi = cc; }
                    }
                    out[(size_t)4 * B + b] = (float)bi;
                }
            }
        }
    }
}

extern "C" void kernel_launch(void* const* d_in, const int* in_sizes, int n_in,
                              void* d_out, int out_size)
{
    const float* x    = (const float*)d_in[0];
    const float* W_ih = (const float*)d_in[1];
    const float* W_hh = (const float*)d_in[2];
    const float* b_ih = (const float*)d_in[3];
    const float* b_hh = (const float*)d_in[4];
    const float* W_fc = (const float*)d_in[5];
    const float* b_fc = (const float*)d_in[6];

    const int B = in_sizes[0] / TT;
    const int threads = 128;
    const int blocks  = (B + SEQ_PER_CTA - 1) / SEQ_PER_CTA;

    lstm_fused_kernel<<<blocks, threads>>>(x, W_ih, W_hh, b_ih, b_hh,
                                           W_fc, b_fc, (float*)d_out, B, out_size);
}